// round 4
// baseline (speedup 1.0000x reference)
#include <cuda_runtime.h>
#include <math.h>
#include <stdint.h>

// ---------------- problem constants ----------------
#define NBATCH   2
#define SEQLEN   512
#define D_INNER  4096
#define D_STATE  16
#define DT_RANK  128
#define NROWS    (NBATCH * SEQLEN)          // 1024
#define XPC      (DT_RANK + 2 * D_STATE)    // 160
#define KSPLIT   8

typedef unsigned long long ull;

// ---------------- scratch ----------------
__device__ float g_part[KSPLIT * NROWS * XPC];
__device__ float g_xp[NROWS * XPC];
__device__ float g_dt[NROWS * D_INNER];

// ---------------- helpers ----------------
__device__ __forceinline__ float ex2f(float v) {
    float r; asm("ex2.approx.ftz.f32 %0, %1;" : "=f"(r) : "f"(v)); return r;
}
__device__ __forceinline__ float softplusf(float z) {
    return fmaxf(z, 0.0f) + log1pf(__expf(-fabsf(z)));
}
__device__ __forceinline__ ull pack2(float lo, float hi) {
    ull r; asm("mov.b64 %0, {%1, %2};" : "=l"(r) : "f"(lo), "f"(hi)); return r;
}
__device__ __forceinline__ float2 unpack2(ull v) {
    float2 f; asm("mov.b64 {%0, %1}, %2;" : "=f"(f.x), "=f"(f.y) : "l"(v)); return f;
}
__device__ __forceinline__ ull fma2(ull a, ull b, ull c) {
    ull d; asm("fma.rn.f32x2 %0, %1, %2, %3;" : "=l"(d) : "l"(a), "l"(b), "l"(c)); return d;
}
__device__ __forceinline__ void cp16(float* dst, const float* src) {
    unsigned s = (unsigned)__cvta_generic_to_shared(dst);
    asm volatile("cp.async.cg.shared.global [%0], [%1], 16;" :: "r"(s), "l"(src));
}
__device__ __forceinline__ void cp_commit() { asm volatile("cp.async.commit_group;"); }
template <int N>
__device__ __forceinline__ void cp_wait() { asm volatile("cp.async.wait_group %0;" :: "n"(N)); }

// =====================================================================
// GEMM1 (FFMA2): part[z][row][c] = sum_{k in slice z} x[row][k]*w[c][k]
// grid(32 Mtiles of 32, 8 ksplit), 256 thr. N=160 full per block.
// micro: 2 rows x 10 cols (5 f32x2 pairs). KC=32, 16 chunks of K=512.
// =====================================================================
__global__ __launch_bounds__(256, 1)
void gemm1_kernel(const float* __restrict__ x, const float* __restrict__ w)
{
    __shared__ float As[32][34];    // [k][row]
    __shared__ float Bs[32][162];   // [k][col]

    const int tid = threadIdx.x;
    const int m0 = blockIdx.x * 32;
    const int kbase = blockIdx.y * 512;

    const int ty = tid >> 4, tx = tid & 15;
    const int r0 = ty * 2, c0 = tx * 10;

    // loaders
    const int ar = tid >> 3;            // 0..31
    const int ak = (tid & 7) * 4;       // 0..28
    const int bq = tid >> 3;            // 0..31 (B base row)
    const float* xg = x + (size_t)(m0 + ar) * D_INNER + kbase + ak;
    const float* wg = w + (size_t)bq * D_INNER + kbase + ak;

    ull acc[2][5];
#pragma unroll
    for (int i = 0; i < 2; i++)
#pragma unroll
        for (int j = 0; j < 5; j++) acc[i][j] = 0ull;

    float4 pa = *(const float4*)xg;
    float4 pb[5];
#pragma unroll
    for (int i = 0; i < 5; i++) pb[i] = *(const float4*)(wg + (size_t)i * 32 * D_INNER);

    for (int c = 0; c < 16; c++) {
        As[ak + 0][ar] = pa.x; As[ak + 1][ar] = pa.y;
        As[ak + 2][ar] = pa.z; As[ak + 3][ar] = pa.w;
#pragma unroll
        for (int i = 0; i < 5; i++) {
            int bc = i * 32 + bq;
            Bs[ak + 0][bc] = pb[i].x; Bs[ak + 1][bc] = pb[i].y;
            Bs[ak + 2][bc] = pb[i].z; Bs[ak + 3][bc] = pb[i].w;
        }
        __syncthreads();

        if (c + 1 < 16) {
            pa = *(const float4*)(xg + (c + 1) * 32);
#pragma unroll
            for (int i = 0; i < 5; i++)
                pb[i] = *(const float4*)(wg + (size_t)i * 32 * D_INNER + (c + 1) * 32);
        }

#pragma unroll
        for (int k = 0; k < 32; k++) {
            float2 a = *(const float2*)&As[k][r0];
            ull a0 = pack2(a.x, a.x);
            ull a1 = pack2(a.y, a.y);
#pragma unroll
            for (int j = 0; j < 5; j++) {
                double bd = *(const double*)&Bs[k][c0 + 2 * j];
                ull b = __double_as_longlong(bd);
                acc[0][j] = fma2(a0, b, acc[0][j]);
                acc[1][j] = fma2(a1, b, acc[1][j]);
            }
        }
        __syncthreads();
    }

    float* outp = g_part + ((size_t)blockIdx.y * NROWS + m0 + r0) * XPC + c0;
#pragma unroll
    for (int i = 0; i < 2; i++)
#pragma unroll
        for (int j = 0; j < 5; j++) {
            float2 v = unpack2(acc[i][j]);
            *(float2*)&outp[(size_t)i * XPC + 2 * j] = v;
        }
}

// =====================================================================
// reduce split-K (vectorized float4)
// =====================================================================
__global__ void reduce_kernel()
{
    int i = blockIdx.x * blockDim.x + threadIdx.x;
    const int n4 = NROWS * XPC / 4;
    if (i < n4) {
        const float4* p = (const float4*)g_part;
        float4 s = p[i];
#pragma unroll
        for (int z = 1; z < KSPLIT; z++) {
            float4 v = p[(size_t)z * n4 + i];
            s.x += v.x; s.y += v.y; s.z += v.z; s.w += v.w;
        }
        ((float4*)g_xp)[i] = s;
    }
}

// =====================================================================
// GEMM2 (FFMA2): g_dt[row][d] = softplus(sum_r xp[row][r]*dtw[d][r] + b[d])
// grid(16 Mtiles of 64, 32 Ntiles of 128), 256 thr.
// micro: 4 rows x 8 cols (4 f32x2 pairs). KC=16, 8 chunks of K=128.
// =====================================================================
__global__ __launch_bounds__(256, 1)
void gemm2_kernel(const float* __restrict__ dtw, const float* __restrict__ dtb)
{
    __shared__ float As[16][68];    // [k][row]
    __shared__ float Bs[16][132];   // [k][col]

    const int tid = threadIdx.x;
    const int m0 = blockIdx.x * 64;
    const int n0 = blockIdx.y * 128;

    const int ty = tid >> 4, tx = tid & 15;
    const int r0 = ty * 4, c0 = tx * 8;

    const int ar = tid >> 2;           // 0..63
    const int ak = (tid & 3) * 4;      // 0..12
    const float* ag = g_xp + (size_t)(m0 + ar) * XPC + ak;
    const float* bg = dtw + (size_t)(n0 + ar) * DT_RANK + ak;    // row group 0
    const float* bg2 = dtw + (size_t)(n0 + 64 + ar) * DT_RANK + ak;

    ull acc[4][4];
#pragma unroll
    for (int i = 0; i < 4; i++)
#pragma unroll
        for (int j = 0; j < 4; j++) acc[i][j] = 0ull;

    float4 pa = *(const float4*)ag;
    float4 pb0 = *(const float4*)bg;
    float4 pb1 = *(const float4*)bg2;

    for (int c = 0; c < 8; c++) {
        As[ak + 0][ar] = pa.x; As[ak + 1][ar] = pa.y;
        As[ak + 2][ar] = pa.z; As[ak + 3][ar] = pa.w;
        Bs[ak + 0][ar] = pb0.x; Bs[ak + 1][ar] = pb0.y;
        Bs[ak + 2][ar] = pb0.z; Bs[ak + 3][ar] = pb0.w;
        Bs[ak + 0][64 + ar] = pb1.x; Bs[ak + 1][64 + ar] = pb1.y;
        Bs[ak + 2][64 + ar] = pb1.z; Bs[ak + 3][64 + ar] = pb1.w;
        __syncthreads();

        if (c + 1 < 8) {
            pa  = *(const float4*)(ag  + (c + 1) * 16);
            pb0 = *(const float4*)(bg  + (c + 1) * 16);
            pb1 = *(const float4*)(bg2 + (c + 1) * 16);
        }

#pragma unroll
        for (int k = 0; k < 16; k++) {
            float4 a = *(const float4*)&As[k][r0];
            ull a0 = pack2(a.x, a.x), a1 = pack2(a.y, a.y);
            ull a2 = pack2(a.z, a.z), a3 = pack2(a.w, a.w);
            double2 bd0 = *(const double2*)&Bs[k][c0];
            double2 bd1 = *(const double2*)&Bs[k][c0 + 4];
            ull b0 = __double_as_longlong(bd0.x), b1 = __double_as_longlong(bd0.y);
            ull b2 = __double_as_longlong(bd1.x), b3 = __double_as_longlong(bd1.y);

            acc[0][0] = fma2(a0, b0, acc[0][0]); acc[0][1] = fma2(a0, b1, acc[0][1]);
            acc[0][2] = fma2(a0, b2, acc[0][2]); acc[0][3] = fma2(a0, b3, acc[0][3]);
            acc[1][0] = fma2(a1, b0, acc[1][0]); acc[1][1] = fma2(a1, b1, acc[1][1]);
            acc[1][2] = fma2(a1, b2, acc[1][2]); acc[1][3] = fma2(a1, b3, acc[1][3]);
            acc[2][0] = fma2(a2, b0, acc[2][0]); acc[2][1] = fma2(a2, b1, acc[2][1]);
            acc[2][2] = fma2(a2, b2, acc[2][2]); acc[2][3] = fma2(a2, b3, acc[2][3]);
            acc[3][0] = fma2(a3, b0, acc[3][0]); acc[3][1] = fma2(a3, b1, acc[3][1]);
            acc[3][2] = fma2(a3, b2, acc[3][2]); acc[3][3] = fma2(a3, b3, acc[3][3]);
        }
        __syncthreads();
    }

    float bias[8];
#pragma unroll
    for (int j = 0; j < 8; j++) bias[j] = dtb[n0 + c0 + j];

#pragma unroll
    for (int i = 0; i < 4; i++) {
        float o[8];
#pragma unroll
        for (int jp = 0; jp < 4; jp++) {
            float2 v = unpack2(acc[i][jp]);
            o[2 * jp + 0] = softplusf(v.x + bias[2 * jp + 0]);
            o[2 * jp + 1] = softplusf(v.y + bias[2 * jp + 1]);
        }
        float* op = &g_dt[(size_t)(m0 + r0 + i) * D_INNER + n0 + c0];
        *(float4*)op = make_float4(o[0], o[1], o[2], o[3]);
        *(float4*)(op + 4) = make_float4(o[4], o[5], o[6], o[7]);
    }
}

// =====================================================================
// Scan: 512 blocks (2 batches x 256 d-tiles of 16 channels), 128 thr.
// 8 lanes per channel, 2 states per lane. cp.async double-buffered.
// =====================================================================
#define LT 64
#define NTILES (SEQLEN / LT)

__global__ __launch_bounds__(128)
void scan_kernel(const float* __restrict__ x, const float* __restrict__ A_log,
                 const float* __restrict__ Dp, float* __restrict__ y)
{
    __shared__ float xs [2 * LT * 16];
    __shared__ float dts[2 * LT * 16];
    __shared__ float Bsm[2 * LT * 16];
    __shared__ float Csm[2 * LT * 16];

    const int tid = threadIdx.x;
    const int b   = blockIdx.x >> 8;
    const int d0  = (blockIdx.x & 255) * 16;
    const int lane = tid & 31;
    const int w    = tid >> 5;
    const int q    = lane & 7;                 // state pair index
    const int cl   = w * 4 + (lane >> 3);      // local channel 0..15
    const int d    = d0 + cl;

    const float LOG2E = 1.4426950408889634f;
    float A2_0 = -__expf(A_log[d * D_STATE + q * 2 + 0]) * LOG2E;
    float A2_1 = -__expf(A_log[d * D_STATE + q * 2 + 1]) * LOG2E;
    const float Dd = Dp[d];

    float h0 = 0.f, h1 = 0.f;

    const float* xg  = x    + (size_t)b * SEQLEN * D_INNER + d0;
    const float* dtg = g_dt + (size_t)b * SEQLEN * D_INNER + d0;
    const float* Bg  = g_xp + (size_t)b * SEQLEN * XPC + DT_RANK;
    const float* Cg  = g_xp + (size_t)b * SEQLEN * XPC + DT_RANK + D_STATE;

    auto load_tile = [&](int t, int buf) {
        const int l0 = t * LT;
        for (int i = tid; i < LT * 4; i += 128) {
            int ll = i >> 2, sg = (i & 3) * 4;
            int so = (buf * LT + ll) * 16 + sg;
            cp16(&xs [so], xg  + (size_t)(l0 + ll) * D_INNER + sg);
            cp16(&dts[so], dtg + (size_t)(l0 + ll) * D_INNER + sg);
            cp16(&Bsm[so], Bg  + (size_t)(l0 + ll) * XPC + sg);
            cp16(&Csm[so], Cg  + (size_t)(l0 + ll) * XPC + sg);
        }
    };

    load_tile(0, 0);
    cp_commit();

    for (int t = 0; t < NTILES; t++) {
        if (t + 1 < NTILES) {
            load_tile(t + 1, (t + 1) & 1);
            cp_commit();
            cp_wait<1>();
        } else {
            cp_wait<0>();
        }
        __syncthreads();

        const int buf = t & 1;
        const float* xsb = &xs [buf * LT * 16];
        const float* dtb_ = &dts[buf * LT * 16];
        const float* Bb  = &Bsm[buf * LT * 16];
        const float* Cb  = &Csm[buf * LT * 16];

        float* yout = y + ((size_t)b * SEQLEN + t * LT) * D_INNER + d;

#pragma unroll 8
        for (int ll = 0; ll < LT; ll++) {
            float dtv = dtb_[ll * 16 + cl];
            float xv  = xsb [ll * 16 + cl];
            float2 Bv = *(const float2*)&Bb[ll * 16 + q * 2];
            float2 Cv = *(const float2*)&Cb[ll * 16 + q * 2];

            float dtx = dtv * xv;
            float e0 = ex2f(dtv * A2_0);
            float e1 = ex2f(dtv * A2_1);
            h0 = fmaf(e0, h0, dtx * Bv.x);
            h1 = fmaf(e1, h1, dtx * Bv.y);

            float p = fmaf(h1, Cv.y, h0 * Cv.x);
            p += __shfl_xor_sync(0xffffffffu, p, 1);
            p += __shfl_xor_sync(0xffffffffu, p, 2);
            p += __shfl_xor_sync(0xffffffffu, p, 4);

            if (q == 0) yout[(size_t)ll * D_INNER] = fmaf(Dd, xv, p);
        }
        __syncthreads();
    }
}

// =====================================================================
// launch
// =====================================================================
extern "C" void kernel_launch(void* const* d_in, const int* in_sizes, int n_in,
                              void* d_out, int out_size)
{
    const float* x     = (const float*)d_in[0];  // (2,512,4096)
    const float* A_log = (const float*)d_in[1];  // (4096,16)
    const float* Dp    = (const float*)d_in[2];  // (4096,)
    const float* xpw   = (const float*)d_in[3];  // (160,4096)
    const float* dtw   = (const float*)d_in[4];  // (4096,128)
    const float* dtb   = (const float*)d_in[5];  // (4096,)
    float* y = (float*)d_out;                    // (2,512,4096)

    gemm1_kernel<<<dim3(32, KSPLIT), 256>>>(x, xpw);
    reduce_kernel<<<(NROWS * XPC / 4 + 255) / 256, 256>>>();
    gemm2_kernel<<<dim3(16, 32), 256>>>(dtw, dtb);
    scan_kernel<<<512, 128>>>(x, A_log, Dp, y);
}

// round 5
// speedup vs baseline: 1.3339x; 1.3339x over previous
#include <cuda_runtime.h>
#include <math.h>
#include <stdint.h>

// ---------------- problem constants ----------------
#define NBATCH   2
#define SEQLEN   512
#define D_INNER  4096
#define D_STATE  16
#define DT_RANK  128
#define NROWS    (NBATCH * SEQLEN)          // 1024
#define XPC      (DT_RANK + 2 * D_STATE)    // 160
#define KSPLIT   16

// ---------------- scratch ----------------
__device__ float g_part[KSPLIT * NROWS * XPC];   // 10.5 MB
__device__ float g_xp[NROWS * XPC];
__device__ float g_dt[NROWS * D_INNER];

// ---------------- helpers ----------------
__device__ __forceinline__ float ex2f(float v) {
    float r; asm("ex2.approx.ftz.f32 %0, %1;" : "=f"(r) : "f"(v)); return r;
}
__device__ __forceinline__ float softplusf(float z) {
    return fmaxf(z, 0.0f) + log1pf(__expf(-fabsf(z)));
}
__device__ __forceinline__ void cp16(float* dst, const float* src) {
    unsigned s = (unsigned)__cvta_generic_to_shared(dst);
    asm volatile("cp.async.cg.shared.global [%0], [%1], 16;" :: "r"(s), "l"(src));
}
__device__ __forceinline__ void cp_commit() { asm volatile("cp.async.commit_group;"); }
template <int N>
__device__ __forceinline__ void cp_wait() { asm volatile("cp.async.wait_group %0;" :: "n"(N)); }

// =====================================================================
// GEMM1: part[z][row][c] = sum_{k in slice z} x[row][k] * w[c][k]
// grid (8 Mtiles of 128, 2 Ntiles of 80, 16 ksplits), 256 thr.
// smem k-major, double-buffered cp.async. micro-tile 8x5. KC=16.
// =====================================================================
#define G1_KC 16
#define G1_CHUNKS 16    // Kslice 256 = 16 * 16

__global__ __launch_bounds__(256, 1)
void gemm1_kernel(const float* __restrict__ x, const float* __restrict__ w)
{
    __shared__ float As[2][G1_KC][132];   // [buf][k][row 0..127 +4 pad]
    __shared__ float Bs[2][G1_KC][84];    // [buf][k][col 0..79  +4 pad]

    const int tid = threadIdx.x;
    const int m0 = blockIdx.x * 128;
    const int n0 = blockIdx.y * 80;
    const int k0 = blockIdx.z * 256;

    const int ty = tid >> 4, tx = tid & 15;
    const int r0 = ty * 8, c0 = tx * 5;

    // loaders: q = k-quad (0..3), r/col = row index
    const int lq = tid & 3;
    const int lr = tid >> 2;              // 0..63

    const float* xg0 = x + (size_t)(m0 + lr) * D_INNER + k0 + lq * 4;
    const float* xg1 = x + (size_t)(m0 + 64 + lr) * D_INNER + k0 + lq * 4;
    const float* wg0 = w + (size_t)(n0 + lr) * D_INNER + k0 + lq * 4;
    const float* wg1 = w + (size_t)(n0 + 64 + lr) * D_INNER + k0 + lq * 4; // tid<64

    auto load_chunk = [&](int c, int buf) {
        const int koff = c * G1_KC;
        cp16(&As[buf][lq * 4][lr],      xg0 + koff);
        cp16(&As[buf][lq * 4][64 + lr], xg1 + koff);
        cp16(&Bs[buf][lq * 4][lr],      wg0 + koff);
        if (tid < 64)
            cp16(&Bs[buf][lq * 4][64 + lr], wg1 + koff);
    };
    // NOTE: cp16 writes 16B along the row dim?? No — it writes 16 contiguous
    // bytes of SMEM, but we need a transpose (global k-contiguous -> smem
    // k-major). cp.async cannot transpose, so stage through registers instead.
    (void)load_chunk;

    float acc[8][5];
#pragma unroll
    for (int i = 0; i < 8; i++)
#pragma unroll
        for (int j = 0; j < 5; j++) acc[i][j] = 0.0f;

    // register-prefetch pipeline (transposing store)
    float4 pa0 = *(const float4*)xg0;
    float4 pa1 = *(const float4*)xg1;
    float4 pb0 = *(const float4*)wg0;
    float4 pb1 = make_float4(0, 0, 0, 0);
    if (tid < 64) pb1 = *(const float4*)wg1;

    for (int c = 0; c < G1_CHUNKS; c++) {
        const int buf = c & 1;
        As[buf][lq * 4 + 0][lr] = pa0.x; As[buf][lq * 4 + 1][lr] = pa0.y;
        As[buf][lq * 4 + 2][lr] = pa0.z; As[buf][lq * 4 + 3][lr] = pa0.w;
        As[buf][lq * 4 + 0][64 + lr] = pa1.x; As[buf][lq * 4 + 1][64 + lr] = pa1.y;
        As[buf][lq * 4 + 2][64 + lr] = pa1.z; As[buf][lq * 4 + 3][64 + lr] = pa1.w;
        Bs[buf][lq * 4 + 0][lr] = pb0.x; Bs[buf][lq * 4 + 1][lr] = pb0.y;
        Bs[buf][lq * 4 + 2][lr] = pb0.z; Bs[buf][lq * 4 + 3][lr] = pb0.w;
        if (tid < 64) {
            Bs[buf][lq * 4 + 0][64 + lr] = pb1.x; Bs[buf][lq * 4 + 1][64 + lr] = pb1.y;
            Bs[buf][lq * 4 + 2][64 + lr] = pb1.z; Bs[buf][lq * 4 + 3][64 + lr] = pb1.w;
        }
        __syncthreads();

        if (c + 1 < G1_CHUNKS) {
            const int koff = (c + 1) * G1_KC;
            pa0 = *(const float4*)(xg0 + koff);
            pa1 = *(const float4*)(xg1 + koff);
            pb0 = *(const float4*)(wg0 + koff);
            if (tid < 64) pb1 = *(const float4*)(wg1 + koff);
        }

#pragma unroll
        for (int k = 0; k < G1_KC; k++) {
            float4 a01 = *(const float4*)&As[buf][k][r0];
            float4 a23 = *(const float4*)&As[buf][k][r0 + 4];
            float a[8] = {a01.x, a01.y, a01.z, a01.w, a23.x, a23.y, a23.z, a23.w};
            float b[5];
#pragma unroll
            for (int j = 0; j < 5; j++) b[j] = Bs[buf][k][c0 + j];
#pragma unroll
            for (int i = 0; i < 8; i++)
#pragma unroll
                for (int j = 0; j < 5; j++)
                    acc[i][j] = fmaf(a[i], b[j], acc[i][j]);
        }
        __syncthreads();
    }

    float* outp = g_part + ((size_t)blockIdx.z * NROWS + m0 + r0) * XPC + n0 + c0;
#pragma unroll
    for (int i = 0; i < 8; i++)
#pragma unroll
        for (int j = 0; j < 5; j++)
            outp[(size_t)i * XPC + j] = acc[i][j];
}

// =====================================================================
// reduce split-K (float4)
// =====================================================================
__global__ void reduce_kernel()
{
    int i = blockIdx.x * blockDim.x + threadIdx.x;
    const int n4 = NROWS * XPC / 4;
    if (i < n4) {
        const float4* p = (const float4*)g_part;
        float4 s = p[i];
#pragma unroll
        for (int z = 1; z < KSPLIT; z++) {
            float4 v = p[(size_t)z * n4 + i];
            s.x += v.x; s.y += v.y; s.z += v.z; s.w += v.w;
        }
        ((float4*)g_xp)[i] = s;
    }
}

// =====================================================================
// GEMM2: g_dt[row][d] = softplus( sum_r xp[row][r]*dtw[d][r] + b[d] )
// grid (8 Mtiles of 128, 32 Ntiles of 128), 256 thr.
// smem k-major, micro-tile 8x8, KC=16, 8 chunks.
// =====================================================================
#define G2_KC 16
#define G2_CHUNKS 8

__global__ __launch_bounds__(256, 1)
void gemm2_kernel(const float* __restrict__ dtw, const float* __restrict__ dtb)
{
    __shared__ float As[2][G2_KC][132];
    __shared__ float Bs[2][G2_KC][132];

    const int tid = threadIdx.x;
    const int m0 = blockIdx.x * 128;
    const int n0 = blockIdx.y * 128;
    const int ty = tid >> 4, tx = tid & 15;
    const int r0 = ty * 8, c0 = tx * 8;

    const int lq = tid & 3;
    const int lr = tid >> 2;

    const float* ag0 = g_xp + (size_t)(m0 + lr) * XPC + lq * 4;
    const float* ag1 = g_xp + (size_t)(m0 + 64 + lr) * XPC + lq * 4;
    const float* bg0 = dtw + (size_t)(n0 + lr) * DT_RANK + lq * 4;
    const float* bg1 = dtw + (size_t)(n0 + 64 + lr) * DT_RANK + lq * 4;

    float acc[8][8];
#pragma unroll
    for (int i = 0; i < 8; i++)
#pragma unroll
        for (int j = 0; j < 8; j++) acc[i][j] = 0.0f;

    float4 pa0 = *(const float4*)ag0;
    float4 pa1 = *(const float4*)ag1;
    float4 pb0 = *(const float4*)bg0;
    float4 pb1 = *(const float4*)bg1;

    for (int c = 0; c < G2_CHUNKS; c++) {
        const int buf = c & 1;
        As[buf][lq * 4 + 0][lr] = pa0.x; As[buf][lq * 4 + 1][lr] = pa0.y;
        As[buf][lq * 4 + 2][lr] = pa0.z; As[buf][lq * 4 + 3][lr] = pa0.w;
        As[buf][lq * 4 + 0][64 + lr] = pa1.x; As[buf][lq * 4 + 1][64 + lr] = pa1.y;
        As[buf][lq * 4 + 2][64 + lr] = pa1.z; As[buf][lq * 4 + 3][64 + lr] = pa1.w;
        Bs[buf][lq * 4 + 0][lr] = pb0.x; Bs[buf][lq * 4 + 1][lr] = pb0.y;
        Bs[buf][lq * 4 + 2][lr] = pb0.z; Bs[buf][lq * 4 + 3][lr] = pb0.w;
        Bs[buf][lq * 4 + 0][64 + lr] = pb1.x; Bs[buf][lq * 4 + 1][64 + lr] = pb1.y;
        Bs[buf][lq * 4 + 2][64 + lr] = pb1.z; Bs[buf][lq * 4 + 3][64 + lr] = pb1.w;
        __syncthreads();

        if (c + 1 < G2_CHUNKS) {
            const int koff = (c + 1) * G2_KC;
            pa0 = *(const float4*)(ag0 + koff);
            pa1 = *(const float4*)(ag1 + koff);
            pb0 = *(const float4*)(bg0 + koff);
            pb1 = *(const float4*)(bg1 + koff);
        }

#pragma unroll
        for (int k = 0; k < G2_KC; k++) {
            float4 a01 = *(const float4*)&As[buf][k][r0];
            float4 a23 = *(const float4*)&As[buf][k][r0 + 4];
            float4 b01 = *(const float4*)&Bs[buf][k][c0];
            float4 b23 = *(const float4*)&Bs[buf][k][c0 + 4];
            float a[8] = {a01.x, a01.y, a01.z, a01.w, a23.x, a23.y, a23.z, a23.w};
            float b[8] = {b01.x, b01.y, b01.z, b01.w, b23.x, b23.y, b23.z, b23.w};
#pragma unroll
            for (int i = 0; i < 8; i++)
#pragma unroll
                for (int j = 0; j < 8; j++)
                    acc[i][j] = fmaf(a[i], b[j], acc[i][j]);
        }
        __syncthreads();
    }

    float bias[8];
#pragma unroll
    for (int j = 0; j < 8; j++) bias[j] = dtb[n0 + c0 + j];

#pragma unroll
    for (int i = 0; i < 8; i++) {
        float o[8];
#pragma unroll
        for (int j = 0; j < 8; j++) o[j] = softplusf(acc[i][j] + bias[j]);
        float* op = &g_dt[(size_t)(m0 + r0 + i) * D_INNER + n0 + c0];
        *(float4*)op = make_float4(o[0], o[1], o[2], o[3]);
        *(float4*)(op + 4) = make_float4(o[4], o[5], o[6], o[7]);
    }
}

// =====================================================================
// Scan (R3 layout): 256 blocks (2 batches x 128 d-tiles of 32 channels),
// 128 thr, 4 lanes/channel, 4 states/lane, cp.async double-buffered.
// =====================================================================
#define LT 64
#define NTILES (SEQLEN / LT)

__global__ __launch_bounds__(128, 4)
void scan_kernel(const float* __restrict__ x, const float* __restrict__ A_log,
                 const float* __restrict__ Dp, float* __restrict__ y)
{
    extern __shared__ float sm[];
    float* xs  = sm;                   // [2][LT][32]
    float* dts = xs + 2 * LT * 32;     // [2][LT][32]
    float* Bsm = dts + 2 * LT * 32;    // [2][LT][16]
    float* Csm = Bsm + 2 * LT * 16;    // [2][LT][16]

    const int tid = threadIdx.x;
    const int b   = blockIdx.x >> 7;
    const int d0  = (blockIdx.x & 127) * 32;
    const int lane = tid & 31;
    const int w    = tid >> 5;
    const int q    = lane & 3;
    const int cl   = w * 8 + (lane >> 2);
    const int d    = d0 + cl;

    float A2[4];
#pragma unroll
    for (int j = 0; j < 4; j++)
        A2[j] = -__expf(A_log[d * D_STATE + q * 4 + j]) * 1.4426950408889634f;
    const float Dd = Dp[d];

    float h0 = 0.f, h1 = 0.f, h2 = 0.f, h3 = 0.f;

    const float* xg  = x    + (size_t)b * SEQLEN * D_INNER + d0;
    const float* dtg = g_dt + (size_t)b * SEQLEN * D_INNER + d0;
    const float* Bg  = g_xp + (size_t)b * SEQLEN * XPC + DT_RANK;
    const float* Cg  = g_xp + (size_t)b * SEQLEN * XPC + DT_RANK + D_STATE;

    auto load_tile = [&](int t, int buf) {
        const int l0 = t * LT;
        for (int i = tid; i < LT * 8; i += 128) {
            int ll = i >> 3, sg = (i & 7) * 4;
            cp16(&xs [(buf * LT + ll) * 32 + sg], xg  + (size_t)(l0 + ll) * D_INNER + sg);
            cp16(&dts[(buf * LT + ll) * 32 + sg], dtg + (size_t)(l0 + ll) * D_INNER + sg);
        }
        for (int i = tid; i < LT * 4; i += 128) {
            int ll = i >> 2, sg = (i & 3) * 4;
            cp16(&Bsm[(buf * LT + ll) * 16 + sg], Bg + (size_t)(l0 + ll) * XPC + sg);
            cp16(&Csm[(buf * LT + ll) * 16 + sg], Cg + (size_t)(l0 + ll) * XPC + sg);
        }
    };

    load_tile(0, 0);
    cp_commit();

    for (int t = 0; t < NTILES; t++) {
        if (t + 1 < NTILES) {
            load_tile(t + 1, (t + 1) & 1);
            cp_commit();
            cp_wait<1>();
        } else {
            cp_wait<0>();
        }
        __syncthreads();

        const int buf = t & 1;
        const float* xsb  = &xs [buf * LT * 32];
        const float* dtb_ = &dts[buf * LT * 32];
        const float* Bb   = &Bsm[buf * LT * 16];
        const float* Cb   = &Csm[buf * LT * 16];

        float* yout = y + ((size_t)b * SEQLEN + t * LT) * D_INNER + d;

#pragma unroll 4
        for (int ll = 0; ll < LT; ll++) {
            float dtv = dtb_[ll * 32 + cl];
            float xv  = xsb [ll * 32 + cl];
            float4 Bv = *(const float4*)&Bb[ll * 16 + q * 4];
            float4 Cv = *(const float4*)&Cb[ll * 16 + q * 4];

            float dtx = dtv * xv;
            float e0 = ex2f(dtv * A2[0]);
            float e1 = ex2f(dtv * A2[1]);
            float e2 = ex2f(dtv * A2[2]);
            float e3 = ex2f(dtv * A2[3]);
            h0 = fmaf(e0, h0, dtx * Bv.x);
            h1 = fmaf(e1, h1, dtx * Bv.y);
            h2 = fmaf(e2, h2, dtx * Bv.z);
            h3 = fmaf(e3, h3, dtx * Bv.w);

            float p = h0 * Cv.x;
            p = fmaf(h1, Cv.y, p);
            p = fmaf(h2, Cv.z, p);
            p = fmaf(h3, Cv.w, p);
            p += __shfl_xor_sync(0xffffffffu, p, 1);
            p += __shfl_xor_sync(0xffffffffu, p, 2);

            if (q == 0) yout[(size_t)ll * D_INNER] = fmaf(Dd, xv, p);
        }
        __syncthreads();
    }
}

// =====================================================================
// launch
// =====================================================================
extern "C" void kernel_launch(void* const* d_in, const int* in_sizes, int n_in,
                              void* d_out, int out_size)
{
    const float* x     = (const float*)d_in[0];  // (2,512,4096)
    const float* A_log = (const float*)d_in[1];  // (4096,16)
    const float* Dp    = (const float*)d_in[2];  // (4096,)
    const float* xpw   = (const float*)d_in[3];  // (160,4096)
    const float* dtw   = (const float*)d_in[4];  // (4096,128)
    const float* dtb   = (const float*)d_in[5];  // (4096,)
    float* y = (float*)d_out;                    // (2,512,4096)

    gemm1_kernel<<<dim3(8, 2, KSPLIT), 256>>>(x, xpw);
    reduce_kernel<<<(NROWS * XPC / 4 + 255) / 256, 256>>>();
    gemm2_kernel<<<dim3(8, 32), 256>>>(dtw, dtb);
    scan_kernel<<<256, 128, 49152>>>(x, A_log, Dp, y);
}